// round 2
// baseline (speedup 1.0000x reference)
#include <cuda_runtime.h>
#include <cstdint>

// Per-channel replacement mask, built each launch (deterministic, graph-capturable).
__device__ int g_mask[512];

// Build mask: zero all 512 entries, then set the replaced channels.
// Indices are int32 (JAX downcasts jnp.int64 -> int32 without x64 mode).
// Single block so __syncthreads orders zero -> scatter. Bounds-guarded scatter.
__global__ void build_mask_kernel(const int* __restrict__ idx, int num_replace, int num_channels)
{
    int t = threadIdx.x;
    if (t < num_channels) g_mask[t] = 0;
    __syncthreads();
    if (t < num_replace) {
        int c = idx[t];
        if (c >= 0 && c < num_channels) g_mask[c] = 1;
    }
}

// Main select kernel: one float4 per thread.
// HW = 28*28 = 784 floats = 196 float4s per (b, c) slice, so each float4 is
// entirely within one channel. channel = (i4 / 196) % 512.
__global__ void __launch_bounds__(256)
replace_kernel(const float4* __restrict__ out_src,
               const float4* __restrict__ feat_src,
               float4* __restrict__ dst,
               int n4)
{
    int i = blockIdx.x * blockDim.x + threadIdx.x;
    if (i >= n4) return;

    int c = (i / 196) & 511;               // channel id (C = 512, power of two)
    // Select the SOURCE POINTER, then do one 128-bit load: we read exactly one
    // of the two tensors (optimal 2x-size total HBM traffic).
    const float4* __restrict__ src = g_mask[c] ? feat_src : out_src;
    dst[i] = src[i];
}

extern "C" void kernel_launch(void* const* d_in, const int* in_sizes, int n_in,
                              void* d_out, int out_size)
{
    const float* out_t  = (const float*)d_in[0];   // output             [32,512,28,28] f32
    const float* feat_t = (const float*)d_in[1];   // matryoshka_features[32,512,28,28] f32
    const int*   idx    = (const int*)d_in[2];     // indices (int32!)   [256]

    const int num_replace  = in_sizes[2];   // 256
    const int num_channels = 512;

    build_mask_kernel<<<1, 512>>>(idx, num_replace, num_channels);

    const int n4 = out_size / 4;            // 12,845,056 / 4 = 3,211,264 float4s
    const int threads = 256;
    const int blocks = (n4 + threads - 1) / threads;   // 12,544
    replace_kernel<<<blocks, threads>>>((const float4*)out_t,
                                        (const float4*)feat_t,
                                        (float4*)d_out,
                                        n4);
}

// round 4
// speedup vs baseline: 1.3643x; 1.3643x over previous
#include <cuda_runtime.h>
#include <cstdint>

// Fused single-kernel feature replacement.
//
// Layout: [B=32, C=512, H*W=784] fp32 -> 196 float4 per (b,c) slice.
// Each block handles 1024 contiguous float4s (4 per thread, 256 threads).
// 1024 divides 512*196 = 100352, so a block never crosses a batch boundary
// and spans at most 7 consecutive channels. The block builds an 8-entry
// shared mask for just those channels from the 256 replacement indices,
// then does a pointer-selected 128-bit copy with ILP=4.

__global__ void __launch_bounds__(256)
fused_replace_kernel(const float4* __restrict__ out_src,
                     const float4* __restrict__ feat_src,
                     float4* __restrict__ dst,
                     const int* __restrict__ idx,
                     int num_replace,
                     int n4)
{
    __shared__ int smask[8];

    const int tid = threadIdx.x;
    const int B0  = blockIdx.x << 10;        // first float4 index of this block
    const int s_lo = B0 / 196;               // first (b,c) slice index
    const int c_base = s_lo & 511;           // its channel (C=512, pow2)

    if (tid < 8) smask[tid] = 0;
    __syncthreads();

    // Mark channels that fall in this block's <=7-channel window.
    // Common case: num_replace <= 256 -> exactly one guarded load per thread.
    if (tid < num_replace) {
        int r = idx[tid] - c_base;           // indices are int32 (JAX x64 off)
        if (r >= 0 && r < 8) smask[r] = 1;
    }
    for (int t = tid + 256; t < num_replace; t += 256) {  // general-case tail
        int r = idx[t] - c_base;
        if (r >= 0 && r < 8) smask[r] = 1;
    }
    __syncthreads();

    const int i0 = B0 + tid;

    // Phase 1: resolve source pointers (shared-mask lookups, cheap).
    const float4* __restrict__ src[4];
#pragma unroll
    for (int k = 0; k < 4; k++) {
        int i = i0 + k * 256;
        int rel = i / 196 - s_lo;            // 0..6 within this block
        src[k] = smask[rel] ? feat_src : out_src;
    }

    // Phase 2: four independent 128-bit loads (MLP=4), then stores.
    float4 v[4];
#pragma unroll
    for (int k = 0; k < 4; k++) {
        int i = i0 + k * 256;
        if (i < n4) v[k] = src[k][i];
    }
#pragma unroll
    for (int k = 0; k < 4; k++) {
        int i = i0 + k * 256;
        if (i < n4) dst[i] = v[k];
    }
}

extern "C" void kernel_launch(void* const* d_in, const int* in_sizes, int n_in,
                              void* d_out, int out_size)
{
    const float* out_t  = (const float*)d_in[0];   // output             [32,512,28,28] f32
    const float* feat_t = (const float*)d_in[1];   // matryoshka_features[32,512,28,28] f32
    const int*   idx    = (const int*)d_in[2];     // indices (int32)    [256]

    const int num_replace = in_sizes[2];           // 256
    const int n4 = out_size / 4;                   // 3,211,264 float4s
    const int blocks = (n4 + 1023) / 1024;         // 3136 (exact)

    fused_replace_kernel<<<blocks, 256>>>((const float4*)out_t,
                                          (const float4*)feat_t,
                                          (float4*)d_out,
                                          idx, num_replace, n4);
}

// round 5
// speedup vs baseline: 1.5439x; 1.1316x over previous
#include <cuda_runtime.h>
#include <cstdint>

// Fused feature replacement, forced-MLP version.
//
// Layout: [B=32, C=512, HW=784] fp32 -> 196 float4 per (b,c) slice.
// Block tile = 2048 contiguous float4s (8 per thread, 256 threads).
// 3,211,264 / 2048 = 1568 blocks exactly -> no bounds guards needed.
// A tile spans <= 11 consecutive channels -> 16-entry shared mask built from
// the 256 replacement indices (one guarded load per thread).
//
// MLP discipline: 8 volatile inline-PTX ld.global.v4 issued before any store
// (volatile asm order survives ptxas), stores use .cs (evict-streaming) so
// dead output lines don't evict the reusable inputs from L2.

__global__ void __launch_bounds__(256)
fused_replace_kernel(const float4* __restrict__ out_src,
                     const float4* __restrict__ feat_src,
                     float4* __restrict__ dst,
                     const int* __restrict__ idx,
                     int num_replace)
{
    __shared__ int smask[16];

    const int tid  = threadIdx.x;
    const int B0   = blockIdx.x << 11;       // first float4 index of this tile
    const int s_lo = B0 / 196;               // first (b,c) slice index
    const int c_base = s_lo & 511;           // its channel (C=512, pow2)

    if (tid < 16) smask[tid] = 0;
    __syncthreads();

    // Mark replaced channels falling inside this tile's <=11-channel window.
    if (tid < num_replace) {
        int r = idx[tid] - c_base;           // indices are int32 (JAX x64 off)
        if (r >= 0 && r < 16) smask[r] = 1;
    }
    for (int t = tid + 256; t < num_replace; t += 256) {   // general tail
        int r = idx[t] - c_base;
        if (r >= 0 && r < 16) smask[r] = 1;
    }
    __syncthreads();

    const int i0 = B0 + tid;

    // Phase 1: resolve the 8 source addresses.
    const float4* src[8];
#pragma unroll
    for (int k = 0; k < 8; k++) {
        int i   = i0 + (k << 8);
        int rel = i / 196 - s_lo;            // 0..10 within this tile
        src[k] = (smask[rel] ? feat_src : out_src) + i;
    }

    // Phase 2: eight independent 128-bit loads, issued back-to-back (MLP=8).
    float4 v[8];
#pragma unroll
    for (int k = 0; k < 8; k++) {
        asm volatile("ld.global.v4.f32 {%0,%1,%2,%3}, [%4];"
                     : "=f"(v[k].x), "=f"(v[k].y), "=f"(v[k].z), "=f"(v[k].w)
                     : "l"(src[k]));
    }

    // Phase 3: streaming stores (output is never re-read; keep inputs in L2).
#pragma unroll
    for (int k = 0; k < 8; k++) {
        __stcs(dst + i0 + (k << 8), v[k]);
    }
}

extern "C" void kernel_launch(void* const* d_in, const int* in_sizes, int n_in,
                              void* d_out, int out_size)
{
    const float* out_t  = (const float*)d_in[0];   // output             [32,512,28,28] f32
    const float* feat_t = (const float*)d_in[1];   // matryoshka_features[32,512,28,28] f32
    const int*   idx    = (const int*)d_in[2];     // indices (int32)    [256]

    const int num_replace = in_sizes[2];           // 256
    const int n4 = out_size / 4;                   // 3,211,264 float4s
    const int blocks = n4 >> 11;                   // 1568 (exact)

    fused_replace_kernel<<<blocks, 256>>>((const float4*)out_t,
                                          (const float4*)feat_t,
                                          (float4*)d_out,
                                          idx, num_replace);
}